// round 12
// baseline (speedup 1.0000x reference)
#include <cuda_runtime.h>
#include <cuda_bf16.h>
#include <math.h>

// ---------------------------------------------------------------------------
// CrossAttentionFusion: fully fused 3-layer transformer (seq=4) on GB300.
// R11 (= R10 design, compile-fixed): 512 threads/CTA (16 warps = 8 n-groups x
// 2 m-halves), vectorized LN (float4 / bf16x2) and float2 residual epilogue.
// ---------------------------------------------------------------------------

#define TS 16          // samples per CTA
#define MROWS 64       // token rows per CTA (= TS*4)
#define DIM 256
#define NTHREADS 512
#define HB_STRIDE 264  // bf16 elems, padded (528B rows: conflict-free ldmatrix)
#define QS 776         // qkv smem stride (768 + 8 pad) -> 1552B rows

#define XS_OFF   0
#define HB_OFF   65536
#define QKV_OFF  99328
#define SMEM_BYTES 198656

// Packed weights, per layer 98304 uint2:
// layout [group][kt][lane][nt] (group = 4 n-tiles = 32 cols; 2048 uint2/group)
// qkv: groups 0..23 (off 0), Wo: off 49152, W1: off 65536, W2: off 81920.
__device__ __align__(16) uint2 g_packed[3 * 98304];

__global__ void pack_all(const float* __restrict__ Wqkv, const float* __restrict__ Wo,
                         const float* __restrict__ W1, const float* __restrict__ W2) {
    int id = blockIdx.x * 256 + threadIdx.x;        // 0 .. 294911
    int l = id / 98304;
    int r = id - l * 98304;
    const float* src;
    int N, idx;
    if (r < 49152)      { src = Wqkv + (size_t)l * 196608; N = 768; idx = r; }
    else if (r < 65536) { src = Wo + (size_t)l * 65536; N = 256; idx = r - 49152; }
    else if (r < 81920) { src = W1 + (size_t)l * 65536; N = 256; idx = r - 65536; }
    else                { src = W2 + (size_t)l * 65536; N = 256; idx = r - 81920; }
    int group = idx >> 11;
    int rem = idx & 2047;
    int kt = rem >> 7;
    int lane = (rem >> 2) & 31;
    int nt = rem & 3;
    int g = lane >> 2, tg = lane & 3;
    int k0 = kt * 16 + tg * 2;
    int n = (group * 4 + nt) * 8 + g;
    unsigned lo0 = __bfloat16_as_ushort(__float2bfloat16(src[(size_t)k0 * N + n]));
    unsigned hi0 = __bfloat16_as_ushort(__float2bfloat16(src[(size_t)(k0 + 1) * N + n]));
    unsigned lo1 = __bfloat16_as_ushort(__float2bfloat16(src[(size_t)(k0 + 8) * N + n]));
    unsigned hi1 = __bfloat16_as_ushort(__float2bfloat16(src[(size_t)(k0 + 9) * N + n]));
    g_packed[id] = make_uint2(lo0 | (hi0 << 16), lo1 | (hi1 << 16));
}

__device__ __forceinline__ float gelu_exact(float v) {
    return 0.5f * v * (1.0f + erff(v * 0.70710678118654752f));
}

__device__ __forceinline__ unsigned bf162_bits(float a, float b) {
    __nv_bfloat162 t = __floats2bfloat162_rn(a, b);
    return *reinterpret_cast<unsigned*>(&t);
}

__device__ __forceinline__ float2 warp_red2(float s, float s2) {
    #pragma unroll
    for (int o = 16; o; o >>= 1) {
        s  += __shfl_xor_sync(0xffffffffu, s, o);
        s2 += __shfl_xor_sync(0xffffffffu, s2, o);
    }
    return make_float2(s, s2);
}

#define MMA_OP(AC, A0, A1, A2, A3, BX, BY)                                     \
    asm volatile(                                                              \
        "mma.sync.aligned.m16n8k16.row.col.f32.bf16.bf16.f32 "                 \
        "{%0,%1,%2,%3}, {%4,%5,%6,%7}, {%8,%9}, {%0,%1,%2,%3};\n"              \
        : "+f"(AC[0]), "+f"(AC[1]), "+f"(AC[2]), "+f"(AC[3])                   \
        : "r"(A0), "r"(A1), "r"(A2), "r"(A3), "r"(BX), "r"(BY))

// ---------------------------------------------------------------------------
// C[64, N] = A[64, 256]_bf16smem @ Wpacked + bias.  16 warps:
// nw = warp&7 owns one 32-col n-group per pass; mw = warp>>3 owns 2 m-tiles.
// A via ldmatrix.x4; B via 2x LDG.128/kt with one-kt-ahead prefetch.
// MODE 0: store bf16 to out; MODE 1: store bf16 gelu(.); MODE 2: xs += (f2).
// ---------------------------------------------------------------------------
template <int MODE>
__device__ __forceinline__ void gemm64(const __nv_bfloat16* __restrict__ A, int lda,
                                       const uint2* __restrict__ W, int N,
                                       const float* __restrict__ bias,
                                       __nv_bfloat16* __restrict__ out, int ostride,
                                       float* __restrict__ xs) {
    const int lane = threadIdx.x & 31, warp = threadIdx.x >> 5;
    const int nw = warp & 7, mw = warp >> 3;
    const int g = lane >> 2, tg = lane & 3;
    const int arow = lane & 15;            // ldmatrix row within m-tile
    const int acol = (lane >> 4) << 3;     // ldmatrix col half-select
    unsigned sbase = (unsigned)__cvta_generic_to_shared(A);
    unsigned amt[2];
    #pragma unroll
    for (int mt = 0; mt < 2; mt++)
        amt[mt] = sbase + (unsigned)((((mw * 2 + mt) * 16 + arow) * lda + acol) * 2);

    const int npasses = N >> 8;
    for (int p = 0; p < npasses; p++) {
        const int grp = p * 8 + nw;
        float acc[2][4][4];  // [mt][nt][frag]
        #pragma unroll
        for (int mt = 0; mt < 2; mt++)
            #pragma unroll
            for (int nt = 0; nt < 4; nt++)
                acc[mt][nt][0] = acc[mt][nt][1] = acc[mt][nt][2] = acc[mt][nt][3] = 0.f;

        // uint4 view: (grp,kt,lane,nt pair) at uint4 idx (grp*16+kt)*64 + lane*2
        const uint4* wp = (const uint4*)W + (size_t)grp * 1024 + lane * 2;
        uint4 b01 = wp[0], b23 = wp[1];
        #pragma unroll
        for (int kt = 0; kt < 16; kt++) {
            uint4 nb01, nb23;
            if (kt < 15) { nb01 = wp[(kt + 1) * 64]; nb23 = wp[(kt + 1) * 64 + 1]; }
            unsigned a[2][4];
            #pragma unroll
            for (int mt = 0; mt < 2; mt++) {
                unsigned aaddr = amt[mt] + (unsigned)(kt * 32);
                asm volatile(
                    "ldmatrix.sync.aligned.m8n8.x4.shared.b16 {%0,%1,%2,%3}, [%4];\n"
                    : "=r"(a[mt][0]), "=r"(a[mt][1]), "=r"(a[mt][2]), "=r"(a[mt][3])
                    : "r"(aaddr));
            }
            #pragma unroll
            for (int mt = 0; mt < 2; mt++) {
                MMA_OP(acc[mt][0], a[mt][0], a[mt][1], a[mt][2], a[mt][3], b01.x, b01.y);
                MMA_OP(acc[mt][1], a[mt][0], a[mt][1], a[mt][2], a[mt][3], b01.z, b01.w);
                MMA_OP(acc[mt][2], a[mt][0], a[mt][1], a[mt][2], a[mt][3], b23.x, b23.y);
                MMA_OP(acc[mt][3], a[mt][0], a[mt][1], a[mt][2], a[mt][3], b23.z, b23.w);
            }
            b01 = nb01; b23 = nb23;
        }
        // epilogue
        #pragma unroll
        for (int nt = 0; nt < 4; nt++) {
            const int cc = (grp * 4 + nt) * 8 + tg * 2;
            const float bb0 = bias[cc], bb1 = bias[cc + 1];
            #pragma unroll
            for (int mt = 0; mt < 2; mt++) {
                const int r0 = (mw * 2 + mt) * 16 + g, r1 = r0 + 8;
                float v00 = acc[mt][nt][0] + bb0, v01 = acc[mt][nt][1] + bb1;
                float v10 = acc[mt][nt][2] + bb0, v11 = acc[mt][nt][3] + bb1;
                if (MODE == 2) {
                    float2* p0 = (float2*)(xs + r0 * DIM + cc);
                    float2* p1 = (float2*)(xs + r1 * DIM + cc);
                    float2 o0 = *p0, o1 = *p1;
                    o0.x += v00; o0.y += v01;
                    o1.x += v10; o1.y += v11;
                    *p0 = o0; *p1 = o1;
                } else {
                    if (MODE == 1) {
                        v00 = gelu_exact(v00); v01 = gelu_exact(v01);
                        v10 = gelu_exact(v10); v11 = gelu_exact(v11);
                    }
                    *(__nv_bfloat162*)(out + r0 * ostride + cc) = __floats2bfloat162_rn(v00, v01);
                    *(__nv_bfloat162*)(out + r1 * ostride + cc) = __floats2bfloat162_rn(v10, v11);
                }
            }
        }
    }
}

// LN all 64 rows of xs -> bf16 dst (gamma/beta per col), float4-vectorized.
__device__ __forceinline__ void ln64_bf16(const float* __restrict__ xs,
                                          const float* __restrict__ gm,
                                          const float* __restrict__ bt,
                                          __nv_bfloat16* __restrict__ dst, int ds) {
    const int lane = threadIdx.x & 31, warp = threadIdx.x >> 5;
    for (int r = warp; r < MROWS; r += 16) {
        const float4* rowv = (const float4*)(xs + r * DIM);
        float4 v0 = rowv[lane], v1 = rowv[lane + 32];
        float s  = v0.x + v0.y + v0.z + v0.w + v1.x + v1.y + v1.z + v1.w;
        float s2 = v0.x * v0.x + v0.y * v0.y + v0.z * v0.z + v0.w * v0.w
                 + v1.x * v1.x + v1.y * v1.y + v1.z * v1.z + v1.w * v1.w;
        float2 rd = warp_red2(s, s2);
        float m = rd.x * (1.f / DIM);
        float var = rd.y * (1.f / DIM) - m * m;
        float rs = rsqrtf(var + 1e-5f);
        #pragma unroll
        for (int i = 0; i < 2; i++) {
            float4 v = i ? v1 : v0;
            int c = (lane + i * 32) * 4;
            float4 gv = *(const float4*)(gm + c);
            float4 bv = *(const float4*)(bt + c);
            float o0 = (v.x - m) * rs * gv.x + bv.x;
            float o1 = (v.y - m) * rs * gv.y + bv.y;
            float o2 = (v.z - m) * rs * gv.z + bv.z;
            float o3 = (v.w - m) * rs * gv.w + bv.w;
            uint2 pk;
            pk.x = bf162_bits(o0, o1);
            pk.y = bf162_bits(o2, o3);
            *(uint2*)(dst + r * ds + c) = pk;
        }
    }
}

__global__ void __launch_bounds__(NTHREADS, 1) fused_kernel(
    const float* __restrict__ ge, const float* __restrict__ pe,
    const float* __restrict__ sfeat, const float* __restrict__ ppi,
    const float* __restrict__ symW, const float* __restrict__ symb,
    const float* __restrict__ symg, const float* __restrict__ symbeta,
    const float* __restrict__ tte,
    const float* __restrict__ bqkv, const float* __restrict__ bo,
    const float* __restrict__ ln1g, const float* __restrict__ ln1b,
    const float* __restrict__ ln2g, const float* __restrict__ ln2b,
    const float* __restrict__ b1, const float* __restrict__ b2,
    const float* __restrict__ flng, const float* __restrict__ flnb,
    const float* __restrict__ olng, const float* __restrict__ olnb,
    float* __restrict__ out) {
    extern __shared__ char smem[];
    float* xs = (float*)(smem + XS_OFF);                       // [64][256] fp32 residual
    __nv_bfloat16* hb = (__nv_bfloat16*)(smem + HB_OFF);       // [64][264] bf16 scratch A
    __nv_bfloat16* qkvb = (__nv_bfloat16*)(smem + QKV_OFF);    // [64][776] bf16 qkv / ff1
    const int tid = threadIdx.x;
    const int lane = tid & 31, warp = tid >> 5;
    const int s0 = blockIdx.x * TS;

    // ---------------- Phase 0: build x = stack(tokens) + tte -------------
    float* sfs = (float*)(smem + QKV_OFF);  // [16][64] sym_feat staging
    for (int idx = tid; idx < TS * 64; idx += NTHREADS) {
        int s = idx >> 6, j = idx & 63;
        sfs[idx] = sfeat[(size_t)(s0 + s) * 64 + j];
    }
    for (int idx = tid; idx < TS * DIM; idx += NTHREADS) {
        int s = idx >> 8, c = idx & 255;
        size_t gsrc = (size_t)(s0 + s) * DIM + c;
        xs[(s * 4 + 0) * DIM + c] = ge[gsrc];
        xs[(s * 4 + 1) * DIM + c] = pe[gsrc];
        xs[(s * 4 + 3) * DIM + c] = ppi[gsrc];
    }
    __syncthreads();
    {   // sym projection: threads 0-255 -> samples 0-7, 256-511 -> samples 8-15
        int c = tid & 255;
        int sb = (tid >> 8) * 8;
        float acc[8];
        #pragma unroll
        for (int s = 0; s < 8; s++) acc[s] = 0.f;
        for (int j = 0; j < 64; j++) {
            float w = symW[(size_t)j * DIM + c];
            #pragma unroll
            for (int s = 0; s < 8; s++) acc[s] += sfs[(sb + s) * 64 + j] * w;
        }
        float bb = symb[c];
        #pragma unroll
        for (int s = 0; s < 8; s++) xs[((sb + s) * 4 + 2) * DIM + c] = acc[s] + bb;
    }
    __syncthreads();
    // sym LN in place on rows 4s+2
    for (int s = warp; s < TS; s += 16) {
        float* row = xs + (s * 4 + 2) * DIM;
        float v[8], su = 0.f, su2 = 0.f;
        #pragma unroll
        for (int i = 0; i < 8; i++) { v[i] = row[lane + i * 32]; su += v[i]; su2 += v[i] * v[i]; }
        float2 rd = warp_red2(su, su2);
        float m = rd.x * (1.f / DIM), var = rd.y * (1.f / DIM) - m * m;
        float rs = rsqrtf(var + 1e-5f);
        #pragma unroll
        for (int i = 0; i < 8; i++) {
            int c = lane + i * 32;
            row[c] = (v[i] - m) * rs * symg[c] + symbeta[c];
        }
    }
    __syncthreads();
    for (int idx = tid; idx < MROWS * DIM; idx += NTHREADS) {
        int r = idx >> 8, c = idx & 255;
        xs[idx] += tte[(r & 3) * DIM + c];
    }
    __syncthreads();

    // ---------------- 3 transformer layers --------------------------------
    for (int l = 0; l < 3; l++) {
        const uint2* pw = g_packed + (size_t)l * 98304;
        ln64_bf16(xs, ln1g + l * DIM, ln1b + l * DIM, hb, HB_STRIDE);
        __syncthreads();
        gemm64<0>(hb, HB_STRIDE, pw, 768, bqkv + l * 768, qkvb, QS, xs);
        __syncthreads();
        // attention: thread = (sample, head); writes o into hb
        if (tid < 128) {
            const int s = tid >> 3, h = tid & 7;
            const __nv_bfloat16* qb = qkvb + (s * 4) * QS + h * 32;
            const __nv_bfloat16* kb = qb + 256;
            const __nv_bfloat16* vb = qb + 512;
            float S[4][4];
            #pragma unroll
            for (int i = 0; i < 4; i++)
                #pragma unroll
                for (int j = 0; j < 4; j++) S[i][j] = 0.f;
            for (int d2 = 0; d2 < 16; d2++) {
                float2 qv[4], kv[4];
                #pragma unroll
                for (int i = 0; i < 4; i++) {
                    qv[i] = __bfloat1622float2(*(const __nv_bfloat162*)(qb + i * QS + d2 * 2));
                    kv[i] = __bfloat1622float2(*(const __nv_bfloat162*)(kb + i * QS + d2 * 2));
                }
                #pragma unroll
                for (int i = 0; i < 4; i++)
                    #pragma unroll
                    for (int j = 0; j < 4; j++)
                        S[i][j] += qv[i].x * kv[j].x + qv[i].y * kv[j].y;
            }
            const float scale = 0.17677669529663687f;  // 1/sqrt(32)
            #pragma unroll
            for (int i = 0; i < 4; i++) {
                float mx = -1e30f;
                #pragma unroll
                for (int j = 0; j < 4; j++) { S[i][j] *= scale; mx = fmaxf(mx, S[i][j]); }
                float sm = 0.f;
                #pragma unroll
                for (int j = 0; j < 4; j++) { S[i][j] = expf(S[i][j] - mx); sm += S[i][j]; }
                float inv = 1.f / sm;
                #pragma unroll
                for (int j = 0; j < 4; j++) S[i][j] *= inv;
            }
            for (int d2 = 0; d2 < 16; d2++) {
                float2 vv[4];
                #pragma unroll
                for (int j = 0; j < 4; j++)
                    vv[j] = __bfloat1622float2(*(const __nv_bfloat162*)(vb + j * QS + d2 * 2));
                #pragma unroll
                for (int i = 0; i < 4; i++) {
                    float ox = 0.f, oy = 0.f;
                    #pragma unroll
                    for (int j = 0; j < 4; j++) { ox += S[i][j] * vv[j].x; oy += S[i][j] * vv[j].y; }
                    *(__nv_bfloat162*)(hb + (s * 4 + i) * HB_STRIDE + h * 32 + d2 * 2) =
                        __floats2bfloat162_rn(ox, oy);
                }
            }
        }
        __syncthreads();
        gemm64<2>(hb, HB_STRIDE, pw + 49152, 256, bo + l * DIM, nullptr, 0, xs);   // x += o @ Wo
        __syncthreads();
        ln64_bf16(xs, ln2g + l * DIM, ln2b + l * DIM, hb, HB_STRIDE);
        __syncthreads();
        gemm64<1>(hb, HB_STRIDE, pw + 65536, 256, b1 + l * DIM, qkvb, QS, xs);     // ff1 = gelu
        __syncthreads();
        gemm64<2>(qkvb, QS, pw + 81920, 256, b2 + l * DIM, nullptr, 0, xs);        // x += ff2
        __syncthreads();
    }

    // ---------------- final LN (in place, fp32) ----------------------------
    for (int r = warp; r < MROWS; r += 16) {
        float* row = xs + r * DIM;
        float v[8], su = 0.f, su2 = 0.f;
        #pragma unroll
        for (int i = 0; i < 8; i++) { v[i] = row[lane + i * 32]; su += v[i]; su2 += v[i] * v[i]; }
        float2 rd = warp_red2(su, su2);
        float m = rd.x * (1.f / DIM), var = rd.y * (1.f / DIM) - m * m;
        float rs = rsqrtf(var + 1e-5f);
        #pragma unroll
        for (int i = 0; i < 8; i++) {
            int c = lane + i * 32;
            row[c] = (v[i] - m) * rs * flng[c] + flnb[c];
        }
    }
    __syncthreads();
    // mean over 4 tokens
    float* ms = (float*)(smem + QKV_OFF);  // [16][256] fp32
    for (int idx = tid; idx < TS * DIM; idx += NTHREADS) {
        int s = idx >> 8, c = idx & 255;
        const float* bp = xs + (s * 4) * DIM + c;
        ms[idx] = 0.25f * (bp[0] + bp[DIM] + bp[2 * DIM] + bp[3 * DIM]);
    }
    __syncthreads();
    // out LN -> global
    for (int r = warp; r < TS; r += 16) {
        const float* row = ms + r * DIM;
        float v[8], su = 0.f, su2 = 0.f;
        #pragma unroll
        for (int i = 0; i < 8; i++) { v[i] = row[lane + i * 32]; su += v[i]; su2 += v[i] * v[i]; }
        float2 rd = warp_red2(su, su2);
        float m = rd.x * (1.f / DIM), var = rd.y * (1.f / DIM) - m * m;
        float rs = rsqrtf(var + 1e-5f);
        #pragma unroll
        for (int i = 0; i < 8; i++) {
            int c = lane + i * 32;
            out[(size_t)(s0 + r) * DIM + c] = (v[i] - m) * rs * olng[c] + olnb[c];
        }
    }
}

extern "C" void kernel_launch(void* const* d_in, const int* in_sizes, int n_in,
                              void* d_out, int out_size) {
    const float* ge      = (const float*)d_in[0];
    const float* pe      = (const float*)d_in[1];
    const float* sfeat   = (const float*)d_in[2];
    const float* ppi     = (const float*)d_in[3];
    const float* symW    = (const float*)d_in[4];
    const float* symb    = (const float*)d_in[5];
    const float* symg    = (const float*)d_in[6];
    const float* symbeta = (const float*)d_in[7];
    const float* tte     = (const float*)d_in[8];
    const float* Wqkv    = (const float*)d_in[9];
    const float* bqkv    = (const float*)d_in[10];
    const float* Wo      = (const float*)d_in[11];
    const float* bo      = (const float*)d_in[12];
    const float* ln1g    = (const float*)d_in[13];
    const float* ln1b    = (const float*)d_in[14];
    const float* ln2g    = (const float*)d_in[15];
    const float* ln2b    = (const float*)d_in[16];
    const float* W1      = (const float*)d_in[17];
    const float* b1      = (const float*)d_in[18];
    const float* W2      = (const float*)d_in[19];
    const float* b2      = (const float*)d_in[20];
    const float* flng    = (const float*)d_in[21];
    const float* flnb    = (const float*)d_in[22];
    const float* olng    = (const float*)d_in[23];
    const float* olnb    = (const float*)d_in[24];

    int B = in_sizes[0] / DIM;

    cudaFuncSetAttribute(fused_kernel, cudaFuncAttributeMaxDynamicSharedMemorySize, SMEM_BYTES);

    pack_all<<<1152, 256>>>(Wqkv, Wo, W1, W2);

    fused_kernel<<<B / TS, NTHREADS, SMEM_BYTES>>>(
        ge, pe, sfeat, ppi, symW, symb, symg, symbeta, tte,
        bqkv, bo, ln1g, ln1b, ln2g, ln2b, b1, b2,
        flng, flnb, olng, olnb, (float*)d_out);
}

// round 13
// speedup vs baseline: 1.2834x; 1.2834x over previous
#include <cuda_runtime.h>
#include <cuda_bf16.h>
#include <math.h>

// ---------------------------------------------------------------------------
// CrossAttentionFusion: fully fused 3-layer transformer (seq=4) on GB300.
// R12: best GEMM config (8 warps, dedup weight fetch, 4 m-tiles/warp) +
// vectorized attention (256 threads, uint4 smem traffic, shfl halves-combine)
// + float4 LayerNorm. Targets the scalar L1 wavefronts ncu showed.
// ---------------------------------------------------------------------------

#define TS 16          // samples per CTA
#define MROWS 64       // token rows per CTA (= TS*4)
#define DIM 256
#define NTHREADS 256
#define HB_STRIDE 264  // bf16 elems, padded (528B rows: conflict-free ldmatrix)
#define QS 776         // qkv smem stride (768 + 8 pad) -> 1552B rows

#define XS_OFF   0
#define HB_OFF   65536
#define QKV_OFF  99328
#define SMEM_BYTES 198656

// Packed weights, per layer 98304 uint2:
// layout [group][kt][lane][nt] (group = 4 n-tiles = 32 cols; 2048 uint2/group)
// qkv: groups 0..23 (off 0), Wo: off 49152, W1: off 65536, W2: off 81920.
__device__ __align__(16) uint2 g_packed[3 * 98304];

__global__ void pack_all(const float* __restrict__ Wqkv, const float* __restrict__ Wo,
                         const float* __restrict__ W1, const float* __restrict__ W2) {
    int id = blockIdx.x * 256 + threadIdx.x;        // 0 .. 294911
    int l = id / 98304;
    int r = id - l * 98304;
    const float* src;
    int N, idx;
    if (r < 49152)      { src = Wqkv + (size_t)l * 196608; N = 768; idx = r; }
    else if (r < 65536) { src = Wo + (size_t)l * 65536; N = 256; idx = r - 49152; }
    else if (r < 81920) { src = W1 + (size_t)l * 65536; N = 256; idx = r - 65536; }
    else                { src = W2 + (size_t)l * 65536; N = 256; idx = r - 81920; }
    int group = idx >> 11;
    int rem = idx & 2047;
    int kt = rem >> 7;
    int lane = (rem >> 2) & 31;
    int nt = rem & 3;
    int g = lane >> 2, tg = lane & 3;
    int k0 = kt * 16 + tg * 2;
    int n = (group * 4 + nt) * 8 + g;
    unsigned lo0 = __bfloat16_as_ushort(__float2bfloat16(src[(size_t)k0 * N + n]));
    unsigned hi0 = __bfloat16_as_ushort(__float2bfloat16(src[(size_t)(k0 + 1) * N + n]));
    unsigned lo1 = __bfloat16_as_ushort(__float2bfloat16(src[(size_t)(k0 + 8) * N + n]));
    unsigned hi1 = __bfloat16_as_ushort(__float2bfloat16(src[(size_t)(k0 + 9) * N + n]));
    g_packed[id] = make_uint2(lo0 | (hi0 << 16), lo1 | (hi1 << 16));
}

__device__ __forceinline__ float gelu_exact(float v) {
    return 0.5f * v * (1.0f + erff(v * 0.70710678118654752f));
}

__device__ __forceinline__ unsigned bf162_bits(float a, float b) {
    __nv_bfloat162 t = __floats2bfloat162_rn(a, b);
    return *reinterpret_cast<unsigned*>(&t);
}

__device__ __forceinline__ float dot2(unsigned a, unsigned b) {
    float2 fa = __bfloat1622float2(*reinterpret_cast<__nv_bfloat162*>(&a));
    float2 fb = __bfloat1622float2(*reinterpret_cast<__nv_bfloat162*>(&b));
    return fa.x * fb.x + fa.y * fb.y;
}

__device__ __forceinline__ float dot8(uint4 a, uint4 b) {
    return dot2(a.x, b.x) + dot2(a.y, b.y) + dot2(a.z, b.z) + dot2(a.w, b.w);
}

__device__ __forceinline__ float2 warp_red2(float s, float s2) {
    #pragma unroll
    for (int o = 16; o; o >>= 1) {
        s  += __shfl_xor_sync(0xffffffffu, s, o);
        s2 += __shfl_xor_sync(0xffffffffu, s2, o);
    }
    return make_float2(s, s2);
}

#define MMA_OP(AC, A0, A1, A2, A3, BX, BY)                                     \
    asm volatile(                                                              \
        "mma.sync.aligned.m16n8k16.row.col.f32.bf16.bf16.f32 "                 \
        "{%0,%1,%2,%3}, {%4,%5,%6,%7}, {%8,%9}, {%0,%1,%2,%3};\n"              \
        : "+f"(AC[0]), "+f"(AC[1]), "+f"(AC[2]), "+f"(AC[3])                   \
        : "r"(A0), "r"(A1), "r"(A2), "r"(A3), "r"(BX), "r"(BY))

// ---------------------------------------------------------------------------
// C[64, N] = A[64, 256]_bf16smem @ Wpacked + bias.  8 warps:
// each warp owns one 32-col group per pass (disjoint -> weights fetched once
// per CTA) and walks all 4 m-tiles; A via ldmatrix.x4; B via 2x LDG.128/kt
// with one-kt-ahead prefetch.
// MODE 0: store bf16 to out; MODE 1: store bf16 gelu(.); MODE 2: xs += (f2).
// ---------------------------------------------------------------------------
template <int MODE>
__device__ __forceinline__ void gemm64(const __nv_bfloat16* __restrict__ A, int lda,
                                       const uint2* __restrict__ W, int N,
                                       const float* __restrict__ bias,
                                       __nv_bfloat16* __restrict__ out, int ostride,
                                       float* __restrict__ xs) {
    const int lane = threadIdx.x & 31, warp = threadIdx.x >> 5;
    const int g = lane >> 2, tg = lane & 3;
    const int arow = lane & 15;            // ldmatrix row within m-tile
    const int acol = (lane >> 4) << 3;     // ldmatrix col half-select
    unsigned sbase = (unsigned)__cvta_generic_to_shared(A);
    unsigned amt[4];
    #pragma unroll
    for (int mt = 0; mt < 4; mt++)
        amt[mt] = sbase + (unsigned)(((mt * 16 + arow) * lda + acol) * 2);

    const int npasses = N >> 8;
    for (int p = 0; p < npasses; p++) {
        const int grp = p * 8 + warp;
        float acc[4][4][4];  // [mt][nt][frag]
        #pragma unroll
        for (int mt = 0; mt < 4; mt++)
            #pragma unroll
            for (int nt = 0; nt < 4; nt++)
                acc[mt][nt][0] = acc[mt][nt][1] = acc[mt][nt][2] = acc[mt][nt][3] = 0.f;

        // uint4 view: (grp,kt,lane,nt pair) at uint4 idx (grp*16+kt)*64 + lane*2
        const uint4* wp = (const uint4*)W + (size_t)grp * 1024 + lane * 2;
        uint4 b01 = wp[0], b23 = wp[1];
        #pragma unroll
        for (int kt = 0; kt < 16; kt++) {
            uint4 nb01, nb23;
            if (kt < 15) { nb01 = wp[(kt + 1) * 64]; nb23 = wp[(kt + 1) * 64 + 1]; }
            unsigned a[4][4];
            #pragma unroll
            for (int mt = 0; mt < 4; mt++) {
                unsigned aaddr = amt[mt] + (unsigned)(kt * 32);
                asm volatile(
                    "ldmatrix.sync.aligned.m8n8.x4.shared.b16 {%0,%1,%2,%3}, [%4];\n"
                    : "=r"(a[mt][0]), "=r"(a[mt][1]), "=r"(a[mt][2]), "=r"(a[mt][3])
                    : "r"(aaddr));
            }
            #pragma unroll
            for (int mt = 0; mt < 4; mt++) {
                MMA_OP(acc[mt][0], a[mt][0], a[mt][1], a[mt][2], a[mt][3], b01.x, b01.y);
                MMA_OP(acc[mt][1], a[mt][0], a[mt][1], a[mt][2], a[mt][3], b01.z, b01.w);
                MMA_OP(acc[mt][2], a[mt][0], a[mt][1], a[mt][2], a[mt][3], b23.x, b23.y);
                MMA_OP(acc[mt][3], a[mt][0], a[mt][1], a[mt][2], a[mt][3], b23.z, b23.w);
            }
            b01 = nb01; b23 = nb23;
        }
        // epilogue
        #pragma unroll
        for (int nt = 0; nt < 4; nt++) {
            const int cc = (grp * 4 + nt) * 8 + tg * 2;
            const float bb0 = bias[cc], bb1 = bias[cc + 1];
            #pragma unroll
            for (int mt = 0; mt < 4; mt++) {
                const int r0 = mt * 16 + g, r1 = r0 + 8;
                float v00 = acc[mt][nt][0] + bb0, v01 = acc[mt][nt][1] + bb1;
                float v10 = acc[mt][nt][2] + bb0, v11 = acc[mt][nt][3] + bb1;
                if (MODE == 2) {
                    float2* p0 = (float2*)(xs + r0 * DIM + cc);
                    float2* p1 = (float2*)(xs + r1 * DIM + cc);
                    float2 o0 = *p0, o1 = *p1;
                    o0.x += v00; o0.y += v01;
                    o1.x += v10; o1.y += v11;
                    *p0 = o0; *p1 = o1;
                } else {
                    if (MODE == 1) {
                        v00 = gelu_exact(v00); v01 = gelu_exact(v01);
                        v10 = gelu_exact(v10); v11 = gelu_exact(v11);
                    }
                    *(__nv_bfloat162*)(out + r0 * ostride + cc) = __floats2bfloat162_rn(v00, v01);
                    *(__nv_bfloat162*)(out + r1 * ostride + cc) = __floats2bfloat162_rn(v10, v11);
                }
            }
        }
    }
}

// LN all 64 rows of xs -> bf16 dst (gamma/beta per col), float4-vectorized.
__device__ __forceinline__ void ln64_bf16(const float* __restrict__ xs,
                                          const float* __restrict__ gm,
                                          const float* __restrict__ bt,
                                          __nv_bfloat16* __restrict__ dst, int ds) {
    const int lane = threadIdx.x & 31, warp = threadIdx.x >> 5;
    for (int r = warp; r < MROWS; r += 8) {
        const float4* rowv = (const float4*)(xs + r * DIM);
        float4 v0 = rowv[lane], v1 = rowv[lane + 32];
        float s  = v0.x + v0.y + v0.z + v0.w + v1.x + v1.y + v1.z + v1.w;
        float s2 = v0.x * v0.x + v0.y * v0.y + v0.z * v0.z + v0.w * v0.w
                 + v1.x * v1.x + v1.y * v1.y + v1.z * v1.z + v1.w * v1.w;
        float2 rd = warp_red2(s, s2);
        float m = rd.x * (1.f / DIM);
        float var = rd.y * (1.f / DIM) - m * m;
        float rs = rsqrtf(var + 1e-5f);
        #pragma unroll
        for (int i = 0; i < 2; i++) {
            float4 v = i ? v1 : v0;
            int c = (lane + i * 32) * 4;
            float4 gv = *(const float4*)(gm + c);
            float4 bv = *(const float4*)(bt + c);
            float o0 = (v.x - m) * rs * gv.x + bv.x;
            float o1 = (v.y - m) * rs * gv.y + bv.y;
            float o2 = (v.z - m) * rs * gv.z + bv.z;
            float o3 = (v.w - m) * rs * gv.w + bv.w;
            uint2 pk;
            pk.x = bf162_bits(o0, o1);
            pk.y = bf162_bits(o2, o3);
            *(uint2*)(dst + r * ds + c) = pk;
        }
    }
}

__global__ void __launch_bounds__(NTHREADS, 1) fused_kernel(
    const float* __restrict__ ge, const float* __restrict__ pe,
    const float* __restrict__ sfeat, const float* __restrict__ ppi,
    const float* __restrict__ symW, const float* __restrict__ symb,
    const float* __restrict__ symg, const float* __restrict__ symbeta,
    const float* __restrict__ tte,
    const float* __restrict__ bqkv, const float* __restrict__ bo,
    const float* __restrict__ ln1g, const float* __restrict__ ln1b,
    const float* __restrict__ ln2g, const float* __restrict__ ln2b,
    const float* __restrict__ b1, const float* __restrict__ b2,
    const float* __restrict__ flng, const float* __restrict__ flnb,
    const float* __restrict__ olng, const float* __restrict__ olnb,
    float* __restrict__ out) {
    extern __shared__ char smem[];
    float* xs = (float*)(smem + XS_OFF);                       // [64][256] fp32 residual
    __nv_bfloat16* hb = (__nv_bfloat16*)(smem + HB_OFF);       // [64][264] bf16 scratch A
    __nv_bfloat16* qkvb = (__nv_bfloat16*)(smem + QKV_OFF);    // [64][776] bf16 qkv / ff1
    const int tid = threadIdx.x;
    const int lane = tid & 31, warp = tid >> 5;
    const int s0 = blockIdx.x * TS;

    // ---------------- Phase 0: build x = stack(tokens) + tte -------------
    float* sfs = (float*)(smem + QKV_OFF);  // [16][64] sym_feat staging
    for (int idx = tid; idx < TS * 64; idx += NTHREADS) {
        int s = idx >> 6, j = idx & 63;
        sfs[idx] = sfeat[(size_t)(s0 + s) * 64 + j];
    }
    for (int idx = tid; idx < TS * DIM; idx += NTHREADS) {
        int s = idx >> 8, c = idx & 255;
        size_t gsrc = (size_t)(s0 + s) * DIM + c;
        xs[(s * 4 + 0) * DIM + c] = ge[gsrc];
        xs[(s * 4 + 1) * DIM + c] = pe[gsrc];
        xs[(s * 4 + 3) * DIM + c] = ppi[gsrc];
    }
    __syncthreads();
    {   // sym projection: thread = output column
        int c = tid;
        float acc[TS];
        #pragma unroll
        for (int s = 0; s < TS; s++) acc[s] = 0.f;
        for (int j = 0; j < 64; j++) {
            float w = symW[(size_t)j * DIM + c];
            #pragma unroll
            for (int s = 0; s < TS; s++) acc[s] += sfs[s * 64 + j] * w;
        }
        float bb = symb[c];
        #pragma unroll
        for (int s = 0; s < TS; s++) xs[(s * 4 + 2) * DIM + c] = acc[s] + bb;
    }
    __syncthreads();
    // sym LN in place on rows 4s+2
    for (int s = warp; s < TS; s += 8) {
        float* row = xs + (s * 4 + 2) * DIM;
        float v[8], su = 0.f, su2 = 0.f;
        #pragma unroll
        for (int i = 0; i < 8; i++) { v[i] = row[lane + i * 32]; su += v[i]; su2 += v[i] * v[i]; }
        float2 rd = warp_red2(su, su2);
        float m = rd.x * (1.f / DIM), var = rd.y * (1.f / DIM) - m * m;
        float rs = rsqrtf(var + 1e-5f);
        #pragma unroll
        for (int i = 0; i < 8; i++) {
            int c = lane + i * 32;
            row[c] = (v[i] - m) * rs * symg[c] + symbeta[c];
        }
    }
    __syncthreads();
    for (int idx = tid; idx < MROWS * DIM; idx += NTHREADS) {
        int r = idx >> 8, c = idx & 255;
        xs[idx] += tte[(r & 3) * DIM + c];
    }
    __syncthreads();

    // ---------------- 3 transformer layers --------------------------------
    for (int l = 0; l < 3; l++) {
        const uint2* pw = g_packed + (size_t)l * 98304;
        ln64_bf16(xs, ln1g + l * DIM, ln1b + l * DIM, hb, HB_STRIDE);
        __syncthreads();
        gemm64<0>(hb, HB_STRIDE, pw, 768, bqkv + l * 768, qkvb, QS, xs);
        __syncthreads();
        // attention: 2 threads per (sample, head), each owns a 16-dim half.
        // All smem traffic via uint4. Halves combined with shfl_xor(1).
        {
            const int u = tid >> 1;          // 0..127 = sample*8 + head
            const int s = u >> 3, h = u & 7;
            const int half = tid & 1;
            const __nv_bfloat16* base = qkvb + (s * 4) * QS + h * 32 + half * 16;
            uint4 q4[4][2];
            #pragma unroll
            for (int i = 0; i < 4; i++) {
                q4[i][0] = *(const uint4*)(base + i * QS);
                q4[i][1] = *(const uint4*)(base + i * QS + 8);
            }
            float S[4][4];
            #pragma unroll
            for (int j = 0; j < 4; j++) {
                uint4 k0 = *(const uint4*)(base + 256 + j * QS);
                uint4 k1 = *(const uint4*)(base + 256 + j * QS + 8);
                #pragma unroll
                for (int i = 0; i < 4; i++)
                    S[i][j] = dot8(q4[i][0], k0) + dot8(q4[i][1], k1);
            }
            #pragma unroll
            for (int i = 0; i < 4; i++)
                #pragma unroll
                for (int j = 0; j < 4; j++)
                    S[i][j] += __shfl_xor_sync(0xffffffffu, S[i][j], 1);
            const float scale = 0.17677669529663687f;  // 1/sqrt(32)
            #pragma unroll
            for (int i = 0; i < 4; i++) {
                float mx = -1e30f;
                #pragma unroll
                for (int j = 0; j < 4; j++) { S[i][j] *= scale; mx = fmaxf(mx, S[i][j]); }
                float sm = 0.f;
                #pragma unroll
                for (int j = 0; j < 4; j++) { S[i][j] = expf(S[i][j] - mx); sm += S[i][j]; }
                float inv = 1.f / sm;
                #pragma unroll
                for (int j = 0; j < 4; j++) S[i][j] *= inv;
            }
            // load v rows (this half's 16 dims) as float2[8]
            float2 vv[4][8];
            #pragma unroll
            for (int j = 0; j < 4; j++) {
                uint4 v0 = *(const uint4*)(base + 512 + j * QS);
                uint4 v1 = *(const uint4*)(base + 512 + j * QS + 8);
                unsigned w0[8] = {v0.x, v0.y, v0.z, v0.w, v1.x, v1.y, v1.z, v1.w};
                #pragma unroll
                for (int d = 0; d < 8; d++)
                    vv[j][d] = __bfloat1622float2(*reinterpret_cast<__nv_bfloat162*>(&w0[d]));
            }
            __nv_bfloat16* ob = hb + h * 32 + half * 16;
            #pragma unroll
            for (int i = 0; i < 4; i++) {
                float ox[8], oy[8];
                #pragma unroll
                for (int d = 0; d < 8; d++) { ox[d] = 0.f; oy[d] = 0.f; }
                #pragma unroll
                for (int j = 0; j < 4; j++) {
                    float sj = S[i][j];
                    #pragma unroll
                    for (int d = 0; d < 8; d++) {
                        ox[d] += sj * vv[j][d].x;
                        oy[d] += sj * vv[j][d].y;
                    }
                }
                uint4 pk0, pk1;
                pk0.x = bf162_bits(ox[0], oy[0]); pk0.y = bf162_bits(ox[1], oy[1]);
                pk0.z = bf162_bits(ox[2], oy[2]); pk0.w = bf162_bits(ox[3], oy[3]);
                pk1.x = bf162_bits(ox[4], oy[4]); pk1.y = bf162_bits(ox[5], oy[5]);
                pk1.z = bf162_bits(ox[6], oy[6]); pk1.w = bf162_bits(ox[7], oy[7]);
                *(uint4*)(ob + (s * 4 + i) * HB_STRIDE) = pk0;
                *(uint4*)(ob + (s * 4 + i) * HB_STRIDE + 8) = pk1;
            }
        }
        __syncthreads();
        gemm64<2>(hb, HB_STRIDE, pw + 49152, 256, bo + l * DIM, nullptr, 0, xs);   // x += o @ Wo
        __syncthreads();
        ln64_bf16(xs, ln2g + l * DIM, ln2b + l * DIM, hb, HB_STRIDE);
        __syncthreads();
        gemm64<1>(hb, HB_STRIDE, pw + 65536, 256, b1 + l * DIM, qkvb, QS, xs);     // ff1 = gelu
        __syncthreads();
        gemm64<2>(qkvb, QS, pw + 81920, 256, b2 + l * DIM, nullptr, 0, xs);        // x += ff2
        __syncthreads();
    }

    // ---------------- final LN (in place, fp32) ----------------------------
    for (int r = warp; r < MROWS; r += 8) {
        float* row = xs + r * DIM;
        float v[8], su = 0.f, su2 = 0.f;
        #pragma unroll
        for (int i = 0; i < 8; i++) { v[i] = row[lane + i * 32]; su += v[i]; su2 += v[i] * v[i]; }
        float2 rd = warp_red2(su, su2);
        float m = rd.x * (1.f / DIM), var = rd.y * (1.f / DIM) - m * m;
        float rs = rsqrtf(var + 1e-5f);
        #pragma unroll
        for (int i = 0; i < 8; i++) {
            int c = lane + i * 32;
            row[c] = (v[i] - m) * rs * flng[c] + flnb[c];
        }
    }
    __syncthreads();
    // mean over 4 tokens
    float* ms = (float*)(smem + QKV_OFF);  // [16][256] fp32
    for (int idx = tid; idx < TS * DIM; idx += NTHREADS) {
        int s = idx >> 8, c = idx & 255;
        const float* bp = xs + (s * 4) * DIM + c;
        ms[idx] = 0.25f * (bp[0] + bp[DIM] + bp[2 * DIM] + bp[3 * DIM]);
    }
    __syncthreads();
    // out LN -> global
    for (int r = warp; r < TS; r += 8) {
        const float* row = ms + r * DIM;
        float v[8], su = 0.f, su2 = 0.f;
        #pragma unroll
        for (int i = 0; i < 8; i++) { v[i] = row[lane + i * 32]; su += v[i]; su2 += v[i] * v[i]; }
        float2 rd = warp_red2(su, su2);
        float m = rd.x * (1.f / DIM), var = rd.y * (1.f / DIM) - m * m;
        float rs = rsqrtf(var + 1e-5f);
        #pragma unroll
        for (int i = 0; i < 8; i++) {
            int c = lane + i * 32;
            out[(size_t)(s0 + r) * DIM + c] = (v[i] - m) * rs * olng[c] + olnb[c];
        }
    }
}

extern "C" void kernel_launch(void* const* d_in, const int* in_sizes, int n_in,
                              void* d_out, int out_size) {
    const float* ge      = (const float*)d_in[0];
    const float* pe      = (const float*)d_in[1];
    const float* sfeat   = (const float*)d_in[2];
    const float* ppi     = (const float*)d_in[3];
    const float* symW    = (const float*)d_in[4];
    const float* symb    = (const float*)d_in[5];
    const float* symg    = (const float*)d_in[6];
    const float* symbeta = (const float*)d_in[7];
    const float* tte     = (const float*)d_in[8];
    const float* Wqkv    = (const float*)d_in[9];
    const float* bqkv    = (const float*)d_in[10];
    const float* Wo      = (const float*)d_in[11];
    const float* bo      = (const float*)d_in[12];
    const float* ln1g    = (const float*)d_in[13];
    const float* ln1b    = (const float*)d_in[14];
    const float* ln2g    = (const float*)d_in[15];
    const float* ln2b    = (const float*)d_in[16];
    const float* W1      = (const float*)d_in[17];
    const float* b1      = (const float*)d_in[18];
    const float* W2      = (const float*)d_in[19];
    const float* b2      = (const float*)d_in[20];
    const float* flng    = (const float*)d_in[21];
    const float* flnb    = (const float*)d_in[22];
    const float* olng    = (const float*)d_in[23];
    const float* olnb    = (const float*)d_in[24];

    int B = in_sizes[0] / DIM;

    cudaFuncSetAttribute(fused_kernel, cudaFuncAttributeMaxDynamicSharedMemorySize, SMEM_BYTES);

    pack_all<<<1152, 256>>>(Wqkv, Wo, W1, W2);

    fused_kernel<<<B / TS, NTHREADS, SMEM_BYTES>>>(
        ge, pe, sfeat, ppi, symW, symb, symg, symbeta, tte,
        bqkv, bo, ln1g, ln1b, ln2g, ln2b, b1, b2,
        flng, flnb, olng, olnb, (float*)d_out);
}

// round 14
// speedup vs baseline: 1.3625x; 1.0616x over previous
#include <cuda_runtime.h>
#include <cuda_bf16.h>
#include <math.h>

// ---------------------------------------------------------------------------
// CrossAttentionFusion: fully fused 3-layer transformer (seq=4) on GB300.
// R13: TS=8 (32 rows/CTA), SMEM 99KB -> 2 CTAs/SM for latency overlap.
// GEMM: 8 warps, dedup weight fetch, 2 m-tiles/warp, ldmatrix.x4 + LDG.128
// prefetch. Attention: 4 threads per (sample,head), uint4 smem traffic.
// ---------------------------------------------------------------------------

#define TS 8           // samples per CTA
#define MROWS 32       // token rows per CTA (= TS*4)
#define DIM 256
#define NTHREADS 256
#define HB_STRIDE 264  // bf16 elems, padded (528B rows: conflict-free ldmatrix)
#define QS 776         // qkv smem stride (768 + 8 pad) -> 1552B rows

#define XS_OFF   0
#define HB_OFF   32768
#define QKV_OFF  49664
#define SMEM_BYTES 99328

// Packed weights, per layer 98304 uint2:
// layout [group][kt][lane][nt] (group = 4 n-tiles = 32 cols; 2048 uint2/group)
// qkv: groups 0..23 (off 0), Wo: off 49152, W1: off 65536, W2: off 81920.
__device__ __align__(16) uint2 g_packed[3 * 98304];

__global__ void pack_all(const float* __restrict__ Wqkv, const float* __restrict__ Wo,
                         const float* __restrict__ W1, const float* __restrict__ W2) {
    int id = blockIdx.x * 256 + threadIdx.x;        // 0 .. 294911
    int l = id / 98304;
    int r = id - l * 98304;
    const float* src;
    int N, idx;
    if (r < 49152)      { src = Wqkv + (size_t)l * 196608; N = 768; idx = r; }
    else if (r < 65536) { src = Wo + (size_t)l * 65536; N = 256; idx = r - 49152; }
    else if (r < 81920) { src = W1 + (size_t)l * 65536; N = 256; idx = r - 65536; }
    else                { src = W2 + (size_t)l * 65536; N = 256; idx = r - 81920; }
    int group = idx >> 11;
    int rem = idx & 2047;
    int kt = rem >> 7;
    int lane = (rem >> 2) & 31;
    int nt = rem & 3;
    int g = lane >> 2, tg = lane & 3;
    int k0 = kt * 16 + tg * 2;
    int n = (group * 4 + nt) * 8 + g;
    unsigned lo0 = __bfloat16_as_ushort(__float2bfloat16(src[(size_t)k0 * N + n]));
    unsigned hi0 = __bfloat16_as_ushort(__float2bfloat16(src[(size_t)(k0 + 1) * N + n]));
    unsigned lo1 = __bfloat16_as_ushort(__float2bfloat16(src[(size_t)(k0 + 8) * N + n]));
    unsigned hi1 = __bfloat16_as_ushort(__float2bfloat16(src[(size_t)(k0 + 9) * N + n]));
    g_packed[id] = make_uint2(lo0 | (hi0 << 16), lo1 | (hi1 << 16));
}

__device__ __forceinline__ float gelu_exact(float v) {
    return 0.5f * v * (1.0f + erff(v * 0.70710678118654752f));
}

__device__ __forceinline__ unsigned bf162_bits(float a, float b) {
    __nv_bfloat162 t = __floats2bfloat162_rn(a, b);
    return *reinterpret_cast<unsigned*>(&t);
}

__device__ __forceinline__ float dot2(unsigned a, unsigned b) {
    float2 fa = __bfloat1622float2(*reinterpret_cast<__nv_bfloat162*>(&a));
    float2 fb = __bfloat1622float2(*reinterpret_cast<__nv_bfloat162*>(&b));
    return fa.x * fb.x + fa.y * fb.y;
}

__device__ __forceinline__ float dot8(uint4 a, uint4 b) {
    return dot2(a.x, b.x) + dot2(a.y, b.y) + dot2(a.z, b.z) + dot2(a.w, b.w);
}

__device__ __forceinline__ float2 warp_red2(float s, float s2) {
    #pragma unroll
    for (int o = 16; o; o >>= 1) {
        s  += __shfl_xor_sync(0xffffffffu, s, o);
        s2 += __shfl_xor_sync(0xffffffffu, s2, o);
    }
    return make_float2(s, s2);
}

#define MMA_OP(AC, A0, A1, A2, A3, BX, BY)                                     \
    asm volatile(                                                              \
        "mma.sync.aligned.m16n8k16.row.col.f32.bf16.bf16.f32 "                 \
        "{%0,%1,%2,%3}, {%4,%5,%6,%7}, {%8,%9}, {%0,%1,%2,%3};\n"              \
        : "+f"(AC[0]), "+f"(AC[1]), "+f"(AC[2]), "+f"(AC[3])                   \
        : "r"(A0), "r"(A1), "r"(A2), "r"(A3), "r"(BX), "r"(BY))

// ---------------------------------------------------------------------------
// C[32, N] = A[32, 256]_bf16smem @ Wpacked + bias.  8 warps:
// each warp owns one 32-col group per pass (disjoint -> weights fetched once
// per CTA) and walks both m-tiles; A via ldmatrix.x4; B via 2x LDG.128/kt
// with one-kt-ahead prefetch.
// MODE 0: store bf16 to out; MODE 1: store bf16 gelu(.); MODE 2: xs += (f2).
// ---------------------------------------------------------------------------
template <int MODE>
__device__ __forceinline__ void gemm32(const __nv_bfloat16* __restrict__ A, int lda,
                                       const uint2* __restrict__ W, int N,
                                       const float* __restrict__ bias,
                                       __nv_bfloat16* __restrict__ out, int ostride,
                                       float* __restrict__ xs) {
    const int lane = threadIdx.x & 31, warp = threadIdx.x >> 5;
    const int g = lane >> 2, tg = lane & 3;
    const int arow = lane & 15;            // ldmatrix row within m-tile
    const int acol = (lane >> 4) << 3;     // ldmatrix col half-select
    unsigned sbase = (unsigned)__cvta_generic_to_shared(A);
    unsigned amt[2];
    #pragma unroll
    for (int mt = 0; mt < 2; mt++)
        amt[mt] = sbase + (unsigned)(((mt * 16 + arow) * lda + acol) * 2);

    const int npasses = N >> 8;
    for (int p = 0; p < npasses; p++) {
        const int grp = p * 8 + warp;
        float acc[2][4][4];  // [mt][nt][frag]
        #pragma unroll
        for (int mt = 0; mt < 2; mt++)
            #pragma unroll
            for (int nt = 0; nt < 4; nt++)
                acc[mt][nt][0] = acc[mt][nt][1] = acc[mt][nt][2] = acc[mt][nt][3] = 0.f;

        // uint4 view: (grp,kt,lane,nt pair) at uint4 idx (grp*16+kt)*64 + lane*2
        const uint4* wp = (const uint4*)W + (size_t)grp * 1024 + lane * 2;
        uint4 b01 = wp[0], b23 = wp[1];
        #pragma unroll
        for (int kt = 0; kt < 16; kt++) {
            uint4 nb01, nb23;
            if (kt < 15) { nb01 = wp[(kt + 1) * 64]; nb23 = wp[(kt + 1) * 64 + 1]; }
            unsigned a[2][4];
            #pragma unroll
            for (int mt = 0; mt < 2; mt++) {
                unsigned aaddr = amt[mt] + (unsigned)(kt * 32);
                asm volatile(
                    "ldmatrix.sync.aligned.m8n8.x4.shared.b16 {%0,%1,%2,%3}, [%4];\n"
                    : "=r"(a[mt][0]), "=r"(a[mt][1]), "=r"(a[mt][2]), "=r"(a[mt][3])
                    : "r"(aaddr));
            }
            #pragma unroll
            for (int mt = 0; mt < 2; mt++) {
                MMA_OP(acc[mt][0], a[mt][0], a[mt][1], a[mt][2], a[mt][3], b01.x, b01.y);
                MMA_OP(acc[mt][1], a[mt][0], a[mt][1], a[mt][2], a[mt][3], b01.z, b01.w);
                MMA_OP(acc[mt][2], a[mt][0], a[mt][1], a[mt][2], a[mt][3], b23.x, b23.y);
                MMA_OP(acc[mt][3], a[mt][0], a[mt][1], a[mt][2], a[mt][3], b23.z, b23.w);
            }
            b01 = nb01; b23 = nb23;
        }
        // epilogue
        #pragma unroll
        for (int nt = 0; nt < 4; nt++) {
            const int cc = (grp * 4 + nt) * 8 + tg * 2;
            const float bb0 = bias[cc], bb1 = bias[cc + 1];
            #pragma unroll
            for (int mt = 0; mt < 2; mt++) {
                const int r0 = mt * 16 + g, r1 = r0 + 8;
                float v00 = acc[mt][nt][0] + bb0, v01 = acc[mt][nt][1] + bb1;
                float v10 = acc[mt][nt][2] + bb0, v11 = acc[mt][nt][3] + bb1;
                if (MODE == 2) {
                    float2* p0 = (float2*)(xs + r0 * DIM + cc);
                    float2* p1 = (float2*)(xs + r1 * DIM + cc);
                    float2 o0 = *p0, o1 = *p1;
                    o0.x += v00; o0.y += v01;
                    o1.x += v10; o1.y += v11;
                    *p0 = o0; *p1 = o1;
                } else {
                    if (MODE == 1) {
                        v00 = gelu_exact(v00); v01 = gelu_exact(v01);
                        v10 = gelu_exact(v10); v11 = gelu_exact(v11);
                    }
                    *(__nv_bfloat162*)(out + r0 * ostride + cc) = __floats2bfloat162_rn(v00, v01);
                    *(__nv_bfloat162*)(out + r1 * ostride + cc) = __floats2bfloat162_rn(v10, v11);
                }
            }
        }
    }
}

// LN all 32 rows of xs -> bf16 dst (gamma/beta per col), float4-vectorized.
__device__ __forceinline__ void ln32_bf16(const float* __restrict__ xs,
                                          const float* __restrict__ gm,
                                          const float* __restrict__ bt,
                                          __nv_bfloat16* __restrict__ dst, int ds) {
    const int lane = threadIdx.x & 31, warp = threadIdx.x >> 5;
    for (int r = warp; r < MROWS; r += 8) {
        const float4* rowv = (const float4*)(xs + r * DIM);
        float4 v0 = rowv[lane], v1 = rowv[lane + 32];
        float s  = v0.x + v0.y + v0.z + v0.w + v1.x + v1.y + v1.z + v1.w;
        float s2 = v0.x * v0.x + v0.y * v0.y + v0.z * v0.z + v0.w * v0.w
                 + v1.x * v1.x + v1.y * v1.y + v1.z * v1.z + v1.w * v1.w;
        float2 rd = warp_red2(s, s2);
        float m = rd.x * (1.f / DIM);
        float var = rd.y * (1.f / DIM) - m * m;
        float rs = rsqrtf(var + 1e-5f);
        #pragma unroll
        for (int i = 0; i < 2; i++) {
            float4 v = i ? v1 : v0;
            int c = (lane + i * 32) * 4;
            float4 gv = *(const float4*)(gm + c);
            float4 bv = *(const float4*)(bt + c);
            float o0 = (v.x - m) * rs * gv.x + bv.x;
            float o1 = (v.y - m) * rs * gv.y + bv.y;
            float o2 = (v.z - m) * rs * gv.z + bv.z;
            float o3 = (v.w - m) * rs * gv.w + bv.w;
            uint2 pk;
            pk.x = bf162_bits(o0, o1);
            pk.y = bf162_bits(o2, o3);
            *(uint2*)(dst + r * ds + c) = pk;
        }
    }
}

__global__ void __launch_bounds__(NTHREADS, 2) fused_kernel(
    const float* __restrict__ ge, const float* __restrict__ pe,
    const float* __restrict__ sfeat, const float* __restrict__ ppi,
    const float* __restrict__ symW, const float* __restrict__ symb,
    const float* __restrict__ symg, const float* __restrict__ symbeta,
    const float* __restrict__ tte,
    const float* __restrict__ bqkv, const float* __restrict__ bo,
    const float* __restrict__ ln1g, const float* __restrict__ ln1b,
    const float* __restrict__ ln2g, const float* __restrict__ ln2b,
    const float* __restrict__ b1, const float* __restrict__ b2,
    const float* __restrict__ flng, const float* __restrict__ flnb,
    const float* __restrict__ olng, const float* __restrict__ olnb,
    float* __restrict__ out) {
    extern __shared__ char smem[];
    float* xs = (float*)(smem + XS_OFF);                       // [32][256] fp32 residual
    __nv_bfloat16* hb = (__nv_bfloat16*)(smem + HB_OFF);       // [32][264] bf16 scratch A
    __nv_bfloat16* qkvb = (__nv_bfloat16*)(smem + QKV_OFF);    // [32][776] bf16 qkv / ff1
    const int tid = threadIdx.x;
    const int lane = tid & 31, warp = tid >> 5;
    const int s0 = blockIdx.x * TS;

    // ---------------- Phase 0: build x = stack(tokens) + tte -------------
    float* sfs = (float*)(smem + QKV_OFF);  // [8][64] sym_feat staging
    for (int idx = tid; idx < TS * 64; idx += NTHREADS) {
        int s = idx >> 6, j = idx & 63;
        sfs[idx] = sfeat[(size_t)(s0 + s) * 64 + j];
    }
    for (int idx = tid; idx < TS * DIM; idx += NTHREADS) {
        int s = idx >> 8, c = idx & 255;
        size_t gsrc = (size_t)(s0 + s) * DIM + c;
        xs[(s * 4 + 0) * DIM + c] = ge[gsrc];
        xs[(s * 4 + 1) * DIM + c] = pe[gsrc];
        xs[(s * 4 + 3) * DIM + c] = ppi[gsrc];
    }
    __syncthreads();
    {   // sym projection: thread = output column, 8 samples each
        int c = tid;
        float acc[TS];
        #pragma unroll
        for (int s = 0; s < TS; s++) acc[s] = 0.f;
        for (int j = 0; j < 64; j++) {
            float w = symW[(size_t)j * DIM + c];
            #pragma unroll
            for (int s = 0; s < TS; s++) acc[s] += sfs[s * 64 + j] * w;
        }
        float bb = symb[c];
        #pragma unroll
        for (int s = 0; s < TS; s++) xs[(s * 4 + 2) * DIM + c] = acc[s] + bb;
    }
    __syncthreads();
    // sym LN in place on rows 4s+2 (one sample per warp)
    for (int s = warp; s < TS; s += 8) {
        float* row = xs + (s * 4 + 2) * DIM;
        float v[8], su = 0.f, su2 = 0.f;
        #pragma unroll
        for (int i = 0; i < 8; i++) { v[i] = row[lane + i * 32]; su += v[i]; su2 += v[i] * v[i]; }
        float2 rd = warp_red2(su, su2);
        float m = rd.x * (1.f / DIM), var = rd.y * (1.f / DIM) - m * m;
        float rs = rsqrtf(var + 1e-5f);
        #pragma unroll
        for (int i = 0; i < 8; i++) {
            int c = lane + i * 32;
            row[c] = (v[i] - m) * rs * symg[c] + symbeta[c];
        }
    }
    __syncthreads();
    for (int idx = tid; idx < MROWS * DIM; idx += NTHREADS) {
        int r = idx >> 8, c = idx & 255;
        xs[idx] += tte[(r & 3) * DIM + c];
    }
    __syncthreads();

    // ---------------- 3 transformer layers --------------------------------
    for (int l = 0; l < 3; l++) {
        const uint2* pw = g_packed + (size_t)l * 98304;
        ln32_bf16(xs, ln1g + l * DIM, ln1b + l * DIM, hb, HB_STRIDE);
        __syncthreads();
        gemm32<0>(hb, HB_STRIDE, pw, 768, bqkv + l * 768, qkvb, QS, xs);
        __syncthreads();
        // attention: 4 threads per (sample, head), each owns an 8-dim quarter.
        // All smem traffic via uint4. Quarters combined with 2-level shfl_xor.
        {
            const int u = tid >> 2;          // 0..63 = sample*8 + head
            const int s = u >> 3, h = u & 7;
            const int qt = tid & 3;
            const __nv_bfloat16* base = qkvb + (s * 4) * QS + h * 32 + qt * 8;
            uint4 q4[4];
            #pragma unroll
            for (int i = 0; i < 4; i++) q4[i] = *(const uint4*)(base + i * QS);
            float S[4][4];
            #pragma unroll
            for (int j = 0; j < 4; j++) {
                uint4 k4 = *(const uint4*)(base + 256 + j * QS);
                #pragma unroll
                for (int i = 0; i < 4; i++) S[i][j] = dot8(q4[i], k4);
            }
            #pragma unroll
            for (int i = 0; i < 4; i++)
                #pragma unroll
                for (int j = 0; j < 4; j++) {
                    S[i][j] += __shfl_xor_sync(0xffffffffu, S[i][j], 1);
                    S[i][j] += __shfl_xor_sync(0xffffffffu, S[i][j], 2);
                }
            const float scale = 0.17677669529663687f;  // 1/sqrt(32)
            #pragma unroll
            for (int i = 0; i < 4; i++) {
                float mx = -1e30f;
                #pragma unroll
                for (int j = 0; j < 4; j++) { S[i][j] *= scale; mx = fmaxf(mx, S[i][j]); }
                float sm = 0.f;
                #pragma unroll
                for (int j = 0; j < 4; j++) { S[i][j] = expf(S[i][j] - mx); sm += S[i][j]; }
                float inv = 1.f / sm;
                #pragma unroll
                for (int j = 0; j < 4; j++) S[i][j] *= inv;
            }
            // v rows: this quarter's 8 dims as 4x float2
            float2 vv[4][4];
            #pragma unroll
            for (int j = 0; j < 4; j++) {
                uint4 v4 = *(const uint4*)(base + 512 + j * QS);
                unsigned w0[4] = {v4.x, v4.y, v4.z, v4.w};
                #pragma unroll
                for (int d = 0; d < 4; d++)
                    vv[j][d] = __bfloat1622float2(*reinterpret_cast<__nv_bfloat162*>(&w0[d]));
            }
            __nv_bfloat16* ob = hb + h * 32 + qt * 8;
            #pragma unroll
            for (int i = 0; i < 4; i++) {
                float ox[4], oy[4];
                #pragma unroll
                for (int d = 0; d < 4; d++) { ox[d] = 0.f; oy[d] = 0.f; }
                #pragma unroll
                for (int j = 0; j < 4; j++) {
                    float sj = S[i][j];
                    #pragma unroll
                    for (int d = 0; d < 4; d++) {
                        ox[d] += sj * vv[j][d].x;
                        oy[d] += sj * vv[j][d].y;
                    }
                }
                uint4 pk;
                pk.x = bf162_bits(ox[0], oy[0]); pk.y = bf162_bits(ox[1], oy[1]);
                pk.z = bf162_bits(ox[2], oy[2]); pk.w = bf162_bits(ox[3], oy[3]);
                *(uint4*)(ob + (s * 4 + i) * HB_STRIDE) = pk;
            }
        }
        __syncthreads();
        gemm32<2>(hb, HB_STRIDE, pw + 49152, 256, bo + l * DIM, nullptr, 0, xs);   // x += o @ Wo
        __syncthreads();
        ln32_bf16(xs, ln2g + l * DIM, ln2b + l * DIM, hb, HB_STRIDE);
        __syncthreads();
        gemm32<1>(hb, HB_STRIDE, pw + 65536, 256, b1 + l * DIM, qkvb, QS, xs);     // ff1 = gelu
        __syncthreads();
        gemm32<2>(qkvb, QS, pw + 81920, 256, b2 + l * DIM, nullptr, 0, xs);        // x += ff2
        __syncthreads();
    }

    // ---------------- final LN (in place, fp32) ----------------------------
    for (int r = warp; r < MROWS; r += 8) {
        float* row = xs + r * DIM;
        float v[8], su = 0.f, su2 = 0.f;
        #pragma unroll
        for (int i = 0; i < 8; i++) { v[i] = row[lane + i * 32]; su += v[i]; su2 += v[i] * v[i]; }
        float2 rd = warp_red2(su, su2);
        float m = rd.x * (1.f / DIM), var = rd.y * (1.f / DIM) - m * m;
        float rs = rsqrtf(var + 1e-5f);
        #pragma unroll
        for (int i = 0; i < 8; i++) {
            int c = lane + i * 32;
            row[c] = (v[i] - m) * rs * flng[c] + flnb[c];
        }
    }
    __syncthreads();
    // mean over 4 tokens
    float* ms = (float*)(smem + QKV_OFF);  // [8][256] fp32
    for (int idx = tid; idx < TS * DIM; idx += NTHREADS) {
        int s = idx >> 8, c = idx & 255;
        const float* bp = xs + (s * 4) * DIM + c;
        ms[idx] = 0.25f * (bp[0] + bp[DIM] + bp[2 * DIM] + bp[3 * DIM]);
    }
    __syncthreads();
    // out LN -> global (one sample per warp)
    for (int r = warp; r < TS; r += 8) {
        const float* row = ms + r * DIM;
        float v[8], su = 0.f, su2 = 0.f;
        #pragma unroll
        for (int i = 0; i < 8; i++) { v[i] = row[lane + i * 32]; su += v[i]; su2 += v[i] * v[i]; }
        float2 rd = warp_red2(su, su2);
        float m = rd.x * (1.f / DIM), var = rd.y * (1.f / DIM) - m * m;
        float rs = rsqrtf(var + 1e-5f);
        #pragma unroll
        for (int i = 0; i < 8; i++) {
            int c = lane + i * 32;
            out[(size_t)(s0 + r) * DIM + c] = (v[i] - m) * rs * olng[c] + olnb[c];
        }
    }
}

extern "C" void kernel_launch(void* const* d_in, const int* in_sizes, int n_in,
                              void* d_out, int out_size) {
    const float* ge      = (const float*)d_in[0];
    const float* pe      = (const float*)d_in[1];
    const float* sfeat   = (const float*)d_in[2];
    const float* ppi     = (const float*)d_in[3];
    const float* symW    = (const float*)d_in[4];
    const float* symb    = (const float*)d_in[5];
    const float* symg    = (const float*)d_in[6];
    const float* symbeta = (const float*)d_in[7];
    const float* tte     = (const float*)d_in[8];
    const float* Wqkv    = (const float*)d_in[9];
    const float* bqkv    = (const float*)d_in[10];
    const float* Wo      = (const float*)d_in[11];
    const float* bo      = (const float*)d_in[12];
    const float* ln1g    = (const float*)d_in[13];
    const float* ln1b    = (const float*)d_in[14];
    const float* ln2g    = (const float*)d_in[15];
    const float* ln2b    = (const float*)d_in[16];
    const float* W1      = (const float*)d_in[17];
    const float* b1      = (const float*)d_in[18];
    const float* W2      = (const float*)d_in[19];
    const float* b2      = (const float*)d_in[20];
    const float* flng    = (const float*)d_in[21];
    const float* flnb    = (const float*)d_in[22];
    const float* olng    = (const float*)d_in[23];
    const float* olnb    = (const float*)d_in[24];

    int B = in_sizes[0] / DIM;

    cudaFuncSetAttribute(fused_kernel, cudaFuncAttributeMaxDynamicSharedMemorySize, SMEM_BYTES);

    pack_all<<<1152, 256>>>(Wqkv, Wo, W1, W2);

    fused_kernel<<<B / TS, NTHREADS, SMEM_BYTES>>>(
        ge, pe, sfeat, ppi, symW, symb, symg, symbeta, tte,
        bqkv, bo, ln1g, ln1b, ln2g, ln2b, b1, b2,
        flng, flnb, olng, olnb, (float*)d_out);
}

// round 15
// speedup vs baseline: 1.6666x; 1.2232x over previous
#include <cuda_runtime.h>
#include <cuda_bf16.h>
#include <math.h>

// ---------------------------------------------------------------------------
// CrossAttentionFusion: fully fused 3-layer transformer (seq=4) on GB300.
// R14: = R13 + (a) weight pack layout [kt][pair][lane] so each B LDG.128 is a
// contiguous 512B warp request (halves B wavefronts), (b) xs stride padded to
// 260 floats to kill 8-way bank conflicts in the residual-add epilogue.
// ---------------------------------------------------------------------------

#define TS 8           // samples per CTA
#define MROWS 32       // token rows per CTA (= TS*4)
#define DIM 256
#define XDIM 260       // xs row stride in floats (1040B: conflict-free-ish)
#define NTHREADS 256
#define HB_STRIDE 264  // bf16 elems, padded (528B rows: conflict-free ldmatrix)
#define QS 776         // qkv smem stride (768 + 8 pad) -> 1552B rows

#define XS_OFF   0
#define HB_OFF   33280
#define QKV_OFF  50176
#define SMEM_BYTES 99840

// Packed weights, per layer 98304 uint2:
// layout [group][kt][pair][lane][half]: uint2 idx within matrix =
//   grp*2048 + kt*128 + (nt>>1)*64 + lane*2 + (nt&1)
// -> per (kt,pair) the 32 lanes' uint4s are CONTIGUOUS 512B.
// qkv: groups 0..23 (off 0), Wo: off 49152, W1: off 65536, W2: off 81920.
__device__ __align__(16) uint2 g_packed[3 * 98304];

__global__ void pack_all(const float* __restrict__ Wqkv, const float* __restrict__ Wo,
                         const float* __restrict__ W1, const float* __restrict__ W2) {
    int id = blockIdx.x * 256 + threadIdx.x;        // 0 .. 294911
    int l = id / 98304;
    int r = id - l * 98304;
    const float* src;
    int N, idx;
    if (r < 49152)      { src = Wqkv + (size_t)l * 196608; N = 768; idx = r; }
    else if (r < 65536) { src = Wo + (size_t)l * 65536; N = 256; idx = r - 49152; }
    else if (r < 81920) { src = W1 + (size_t)l * 65536; N = 256; idx = r - 65536; }
    else                { src = W2 + (size_t)l * 65536; N = 256; idx = r - 81920; }
    int group = idx >> 11;
    int rem = idx & 2047;
    int kt = rem >> 7;
    int lane = (rem >> 2) & 31;
    int nt = rem & 3;
    int g = lane >> 2, tg = lane & 3;
    int k0 = kt * 16 + tg * 2;
    int n = (group * 4 + nt) * 8 + g;
    unsigned lo0 = __bfloat16_as_ushort(__float2bfloat16(src[(size_t)k0 * N + n]));
    unsigned hi0 = __bfloat16_as_ushort(__float2bfloat16(src[(size_t)(k0 + 1) * N + n]));
    unsigned lo1 = __bfloat16_as_ushort(__float2bfloat16(src[(size_t)(k0 + 8) * N + n]));
    unsigned hi1 = __bfloat16_as_ushort(__float2bfloat16(src[(size_t)(k0 + 9) * N + n]));
    // new contiguous-per-(kt,pair) output index
    int out_idx = (id - r) + group * 2048 + kt * 128 + (nt >> 1) * 64 + lane * 2 + (nt & 1)
                + (idx != r ? 0 : 0);
    // region base within layer: r - idx gives matrix offset; add layer base
    out_idx = l * 98304 + (r - idx) + group * 2048 + kt * 128 + (nt >> 1) * 64 + lane * 2 + (nt & 1);
    g_packed[out_idx] = make_uint2(lo0 | (hi0 << 16), lo1 | (hi1 << 16));
}

__device__ __forceinline__ float gelu_exact(float v) {
    return 0.5f * v * (1.0f + erff(v * 0.70710678118654752f));
}

__device__ __forceinline__ unsigned bf162_bits(float a, float b) {
    __nv_bfloat162 t = __floats2bfloat162_rn(a, b);
    return *reinterpret_cast<unsigned*>(&t);
}

__device__ __forceinline__ float dot2(unsigned a, unsigned b) {
    float2 fa = __bfloat1622float2(*reinterpret_cast<__nv_bfloat162*>(&a));
    float2 fb = __bfloat1622float2(*reinterpret_cast<__nv_bfloat162*>(&b));
    return fa.x * fb.x + fa.y * fb.y;
}

__device__ __forceinline__ float dot8(uint4 a, uint4 b) {
    return dot2(a.x, b.x) + dot2(a.y, b.y) + dot2(a.z, b.z) + dot2(a.w, b.w);
}

__device__ __forceinline__ float2 warp_red2(float s, float s2) {
    #pragma unroll
    for (int o = 16; o; o >>= 1) {
        s  += __shfl_xor_sync(0xffffffffu, s, o);
        s2 += __shfl_xor_sync(0xffffffffu, s2, o);
    }
    return make_float2(s, s2);
}

#define MMA_OP(AC, A0, A1, A2, A3, BX, BY)                                     \
    asm volatile(                                                              \
        "mma.sync.aligned.m16n8k16.row.col.f32.bf16.bf16.f32 "                 \
        "{%0,%1,%2,%3}, {%4,%5,%6,%7}, {%8,%9}, {%0,%1,%2,%3};\n"              \
        : "+f"(AC[0]), "+f"(AC[1]), "+f"(AC[2]), "+f"(AC[3])                   \
        : "r"(A0), "r"(A1), "r"(A2), "r"(A3), "r"(BX), "r"(BY))

// ---------------------------------------------------------------------------
// C[32, N] = A[32, 256]_bf16smem @ Wpacked + bias.  8 warps:
// each warp owns one 32-col group per pass (disjoint -> weights fetched once
// per CTA) and walks both m-tiles; A via ldmatrix.x4; B via 2x contiguous
// LDG.128/kt with one-kt-ahead prefetch.
// MODE 0: store bf16 to out; MODE 1: store bf16 gelu(.); MODE 2: xs += (f2).
// ---------------------------------------------------------------------------
template <int MODE>
__device__ __forceinline__ void gemm32(const __nv_bfloat16* __restrict__ A, int lda,
                                       const uint2* __restrict__ W, int N,
                                       const float* __restrict__ bias,
                                       __nv_bfloat16* __restrict__ out, int ostride,
                                       float* __restrict__ xs) {
    const int lane = threadIdx.x & 31, warp = threadIdx.x >> 5;
    const int g = lane >> 2, tg = lane & 3;
    const int arow = lane & 15;            // ldmatrix row within m-tile
    const int acol = (lane >> 4) << 3;     // ldmatrix col half-select
    unsigned sbase = (unsigned)__cvta_generic_to_shared(A);
    unsigned amt[2];
    #pragma unroll
    for (int mt = 0; mt < 2; mt++)
        amt[mt] = sbase + (unsigned)(((mt * 16 + arow) * lda + acol) * 2);

    const int npasses = N >> 8;
    for (int p = 0; p < npasses; p++) {
        const int grp = p * 8 + warp;
        float acc[2][4][4];  // [mt][nt][frag]
        #pragma unroll
        for (int mt = 0; mt < 2; mt++)
            #pragma unroll
            for (int nt = 0; nt < 4; nt++)
                acc[mt][nt][0] = acc[mt][nt][1] = acc[mt][nt][2] = acc[mt][nt][3] = 0.f;

        // uint4 view: (grp,kt,pair,lane) at uint4 idx grp*1024 + kt*64 + pair*32 + lane
        const uint4* wp = (const uint4*)W + (size_t)grp * 1024 + lane;
        uint4 b01 = wp[0], b23 = wp[32];
        #pragma unroll
        for (int kt = 0; kt < 16; kt++) {
            uint4 nb01, nb23;
            if (kt < 15) { nb01 = wp[(kt + 1) * 64]; nb23 = wp[(kt + 1) * 64 + 32]; }
            unsigned a[2][4];
            #pragma unroll
            for (int mt = 0; mt < 2; mt++) {
                unsigned aaddr = amt[mt] + (unsigned)(kt * 32);
                asm volatile(
                    "ldmatrix.sync.aligned.m8n8.x4.shared.b16 {%0,%1,%2,%3}, [%4];\n"
                    : "=r"(a[mt][0]), "=r"(a[mt][1]), "=r"(a[mt][2]), "=r"(a[mt][3])
                    : "r"(aaddr));
            }
            #pragma unroll
            for (int mt = 0; mt < 2; mt++) {
                MMA_OP(acc[mt][0], a[mt][0], a[mt][1], a[mt][2], a[mt][3], b01.x, b01.y);
                MMA_OP(acc[mt][1], a[mt][0], a[mt][1], a[mt][2], a[mt][3], b01.z, b01.w);
                MMA_OP(acc[mt][2], a[mt][0], a[mt][1], a[mt][2], a[mt][3], b23.x, b23.y);
                MMA_OP(acc[mt][3], a[mt][0], a[mt][1], a[mt][2], a[mt][3], b23.z, b23.w);
            }
            b01 = nb01; b23 = nb23;
        }
        // epilogue
        #pragma unroll
        for (int nt = 0; nt < 4; nt++) {
            const int cc = (grp * 4 + nt) * 8 + tg * 2;
            const float bb0 = bias[cc], bb1 = bias[cc + 1];
            #pragma unroll
            for (int mt = 0; mt < 2; mt++) {
                const int r0 = mt * 16 + g, r1 = r0 + 8;
                float v00 = acc[mt][nt][0] + bb0, v01 = acc[mt][nt][1] + bb1;
                float v10 = acc[mt][nt][2] + bb0, v11 = acc[mt][nt][3] + bb1;
                if (MODE == 2) {
                    float2* p0 = (float2*)(xs + r0 * XDIM + cc);
                    float2* p1 = (float2*)(xs + r1 * XDIM + cc);
                    float2 o0 = *p0, o1 = *p1;
                    o0.x += v00; o0.y += v01;
                    o1.x += v10; o1.y += v11;
                    *p0 = o0; *p1 = o1;
                } else {
                    if (MODE == 1) {
                        v00 = gelu_exact(v00); v01 = gelu_exact(v01);
                        v10 = gelu_exact(v10); v11 = gelu_exact(v11);
                    }
                    *(__nv_bfloat162*)(out + r0 * ostride + cc) = __floats2bfloat162_rn(v00, v01);
                    *(__nv_bfloat162*)(out + r1 * ostride + cc) = __floats2bfloat162_rn(v10, v11);
                }
            }
        }
    }
}

// LN all 32 rows of xs -> bf16 dst (gamma/beta per col), float4-vectorized.
__device__ __forceinline__ void ln32_bf16(const float* __restrict__ xs,
                                          const float* __restrict__ gm,
                                          const float* __restrict__ bt,
                                          __nv_bfloat16* __restrict__ dst, int ds) {
    const int lane = threadIdx.x & 31, warp = threadIdx.x >> 5;
    for (int r = warp; r < MROWS; r += 8) {
        const float4* rowv = (const float4*)(xs + r * XDIM);
        float4 v0 = rowv[lane], v1 = rowv[lane + 32];
        float s  = v0.x + v0.y + v0.z + v0.w + v1.x + v1.y + v1.z + v1.w;
        float s2 = v0.x * v0.x + v0.y * v0.y + v0.z * v0.z + v0.w * v0.w
                 + v1.x * v1.x + v1.y * v1.y + v1.z * v1.z + v1.w * v1.w;
        float2 rd = warp_red2(s, s2);
        float m = rd.x * (1.f / DIM);
        float var = rd.y * (1.f / DIM) - m * m;
        float rs = rsqrtf(var + 1e-5f);
        #pragma unroll
        for (int i = 0; i < 2; i++) {
            float4 v = i ? v1 : v0;
            int c = (lane + i * 32) * 4;
            float4 gv = *(const float4*)(gm + c);
            float4 bv = *(const float4*)(bt + c);
            float o0 = (v.x - m) * rs * gv.x + bv.x;
            float o1 = (v.y - m) * rs * gv.y + bv.y;
            float o2 = (v.z - m) * rs * gv.z + bv.z;
            float o3 = (v.w - m) * rs * gv.w + bv.w;
            uint2 pk;
            pk.x = bf162_bits(o0, o1);
            pk.y = bf162_bits(o2, o3);
            *(uint2*)(dst + r * ds + c) = pk;
        }
    }
}

__global__ void __launch_bounds__(NTHREADS, 2) fused_kernel(
    const float* __restrict__ ge, const float* __restrict__ pe,
    const float* __restrict__ sfeat, const float* __restrict__ ppi,
    const float* __restrict__ symW, const float* __restrict__ symb,
    const float* __restrict__ symg, const float* __restrict__ symbeta,
    const float* __restrict__ tte,
    const float* __restrict__ bqkv, const float* __restrict__ bo,
    const float* __restrict__ ln1g, const float* __restrict__ ln1b,
    const float* __restrict__ ln2g, const float* __restrict__ ln2b,
    const float* __restrict__ b1, const float* __restrict__ b2,
    const float* __restrict__ flng, const float* __restrict__ flnb,
    const float* __restrict__ olng, const float* __restrict__ olnb,
    float* __restrict__ out) {
    extern __shared__ char smem[];
    float* xs = (float*)(smem + XS_OFF);                       // [32][260] fp32 residual
    __nv_bfloat16* hb = (__nv_bfloat16*)(smem + HB_OFF);       // [32][264] bf16 scratch A
    __nv_bfloat16* qkvb = (__nv_bfloat16*)(smem + QKV_OFF);    // [32][776] bf16 qkv / ff1
    const int tid = threadIdx.x;
    const int lane = tid & 31, warp = tid >> 5;
    const int s0 = blockIdx.x * TS;

    // ---------------- Phase 0: build x = stack(tokens) + tte -------------
    float* sfs = (float*)(smem + QKV_OFF);  // [8][64] sym_feat staging
    for (int idx = tid; idx < TS * 64; idx += NTHREADS) {
        int s = idx >> 6, j = idx & 63;
        sfs[idx] = sfeat[(size_t)(s0 + s) * 64 + j];
    }
    for (int idx = tid; idx < TS * DIM; idx += NTHREADS) {
        int s = idx >> 8, c = idx & 255;
        size_t gsrc = (size_t)(s0 + s) * DIM + c;
        xs[(s * 4 + 0) * XDIM + c] = ge[gsrc];
        xs[(s * 4 + 1) * XDIM + c] = pe[gsrc];
        xs[(s * 4 + 3) * XDIM + c] = ppi[gsrc];
    }
    __syncthreads();
    {   // sym projection: thread = output column, 8 samples each
        int c = tid;
        float acc[TS];
        #pragma unroll
        for (int s = 0; s < TS; s++) acc[s] = 0.f;
        for (int j = 0; j < 64; j++) {
            float w = symW[(size_t)j * DIM + c];
            #pragma unroll
            for (int s = 0; s < TS; s++) acc[s] += sfs[s * 64 + j] * w;
        }
        float bb = symb[c];
        #pragma unroll
        for (int s = 0; s < TS; s++) xs[(s * 4 + 2) * XDIM + c] = acc[s] + bb;
    }
    __syncthreads();
    // sym LN in place on rows 4s+2 (one sample per warp)
    for (int s = warp; s < TS; s += 8) {
        float* row = xs + (s * 4 + 2) * XDIM;
        float v[8], su = 0.f, su2 = 0.f;
        #pragma unroll
        for (int i = 0; i < 8; i++) { v[i] = row[lane + i * 32]; su += v[i]; su2 += v[i] * v[i]; }
        float2 rd = warp_red2(su, su2);
        float m = rd.x * (1.f / DIM), var = rd.y * (1.f / DIM) - m * m;
        float rs = rsqrtf(var + 1e-5f);
        #pragma unroll
        for (int i = 0; i < 8; i++) {
            int c = lane + i * 32;
            row[c] = (v[i] - m) * rs * symg[c] + symbeta[c];
        }
    }
    __syncthreads();
    for (int idx = tid; idx < MROWS * DIM; idx += NTHREADS) {
        int r = idx >> 8, c = idx & 255;
        xs[r * XDIM + c] += tte[(r & 3) * DIM + c];
    }
    __syncthreads();

    // ---------------- 3 transformer layers --------------------------------
    for (int l = 0; l < 3; l++) {
        const uint2* pw = g_packed + (size_t)l * 98304;
        ln32_bf16(xs, ln1g + l * DIM, ln1b + l * DIM, hb, HB_STRIDE);
        __syncthreads();
        gemm32<0>(hb, HB_STRIDE, pw, 768, bqkv + l * 768, qkvb, QS, xs);
        __syncthreads();
        // attention: 4 threads per (sample, head), each owns an 8-dim quarter.
        // All smem traffic via uint4. Quarters combined with 2-level shfl_xor.
        {
            const int u = tid >> 2;          // 0..63 = sample*8 + head
            const int s = u >> 3, h = u & 7;
            const int qt = tid & 3;
            const __nv_bfloat16* base = qkvb + (s * 4) * QS + h * 32 + qt * 8;
            uint4 q4[4];
            #pragma unroll
            for (int i = 0; i < 4; i++) q4[i] = *(const uint4*)(base + i * QS);
            float S[4][4];
            #pragma unroll
            for (int j = 0; j < 4; j++) {
                uint4 k4 = *(const uint4*)(base + 256 + j * QS);
                #pragma unroll
                for (int i = 0; i < 4; i++) S[i][j] = dot8(q4[i], k4);
            }
            #pragma unroll
            for (int i = 0; i < 4; i++)
                #pragma unroll
                for (int j = 0; j < 4; j++) {
                    S[i][j] += __shfl_xor_sync(0xffffffffu, S[i][j], 1);
                    S[i][j] += __shfl_xor_sync(0xffffffffu, S[i][j], 2);
                }
            const float scale = 0.17677669529663687f;  // 1/sqrt(32)
            #pragma unroll
            for (int i = 0; i < 4; i++) {
                float mx = -1e30f;
                #pragma unroll
                for (int j = 0; j < 4; j++) { S[i][j] *= scale; mx = fmaxf(mx, S[i][j]); }
                float sm = 0.f;
                #pragma unroll
                for (int j = 0; j < 4; j++) { S[i][j] = expf(S[i][j] - mx); sm += S[i][j]; }
                float inv = 1.f / sm;
                #pragma unroll
                for (int j = 0; j < 4; j++) S[i][j] *= inv;
            }
            // v rows: this quarter's 8 dims as 4x float2
            float2 vv[4][4];
            #pragma unroll
            for (int j = 0; j < 4; j++) {
                uint4 v4 = *(const uint4*)(base + 512 + j * QS);
                unsigned w0[4] = {v4.x, v4.y, v4.z, v4.w};
                #pragma unroll
                for (int d = 0; d < 4; d++)
                    vv[j][d] = __bfloat1622float2(*reinterpret_cast<__nv_bfloat162*>(&w0[d]));
            }
            __nv_bfloat16* ob = hb + h * 32 + qt * 8;
            #pragma unroll
            for (int i = 0; i < 4; i++) {
                float ox[4], oy[4];
                #pragma unroll
                for (int d = 0; d < 4; d++) { ox[d] = 0.f; oy[d] = 0.f; }
                #pragma unroll
                for (int j = 0; j < 4; j++) {
                    float sj = S[i][j];
                    #pragma unroll
                    for (int d = 0; d < 4; d++) {
                        ox[d] += sj * vv[j][d].x;
                        oy[d] += sj * vv[j][d].y;
                    }
                }
                uint4 pk;
                pk.x = bf162_bits(ox[0], oy[0]); pk.y = bf162_bits(ox[1], oy[1]);
                pk.z = bf162_bits(ox[2], oy[2]); pk.w = bf162_bits(ox[3], oy[3]);
                *(uint4*)(ob + (s * 4 + i) * HB_STRIDE) = pk;
            }
        }
        __syncthreads();
        gemm32<2>(hb, HB_STRIDE, pw + 49152, 256, bo + l * DIM, nullptr, 0, xs);   // x += o @ Wo
        __syncthreads();
        ln32_bf16(xs, ln2g + l * DIM, ln2b + l * DIM, hb, HB_STRIDE);
        __syncthreads();
        gemm32<1>(hb, HB_STRIDE, pw + 65536, 256, b1 + l * DIM, qkvb, QS, xs);     // ff1 = gelu
        __syncthreads();
        gemm32<2>(qkvb, QS, pw + 81920, 256, b2 + l * DIM, nullptr, 0, xs);        // x += ff2
        __syncthreads();
    }

    // ---------------- final LN (in place, fp32) ----------------------------
    for (int r = warp; r < MROWS; r += 8) {
        float* row = xs + r * XDIM;
        float v[8], su = 0.f, su2 = 0.f;
        #pragma unroll
        for (int i = 0; i < 8; i++) { v[i] = row[lane + i * 32]; su += v[i]; su2 += v[i] * v[i]; }
        float2 rd = warp_red2(su, su2);
        float m = rd.x * (1.f / DIM), var = rd.y * (1.f / DIM) - m * m;
        float rs = rsqrtf(var + 1e-5f);
        #pragma unroll
        for (int i = 0; i < 8; i++) {
            int c = lane + i * 32;
            row[c] = (v[i] - m) * rs * flng[c] + flnb[c];
        }
    }
    __syncthreads();
    // mean over 4 tokens
    float* ms = (float*)(smem + QKV_OFF);  // [8][256] fp32
    for (int idx = tid; idx < TS * DIM; idx += NTHREADS) {
        int s = idx >> 8, c = idx & 255;
        const float* bp = xs + (s * 4) * XDIM + c;
        ms[idx] = 0.25f * (bp[0] + bp[XDIM] + bp[2 * XDIM] + bp[3 * XDIM]);
    }
    __syncthreads();
    // out LN -> global (one sample per warp)
    for (int r = warp; r < TS; r += 8) {
        const float* row = ms + r * DIM;
        float v[8], su = 0.f, su2 = 0.f;
        #pragma unroll
        for (int i = 0; i < 8; i++) { v[i] = row[lane + i * 32]; su += v[i]; su2 += v[i] * v[i]; }
        float2 rd = warp_red2(su, su2);
        float m = rd.x * (1.f / DIM), var = rd.y * (1.f / DIM) - m * m;
        float rs = rsqrtf(var + 1e-5f);
        #pragma unroll
        for (int i = 0; i < 8; i++) {
            int c = lane + i * 32;
            out[(size_t)(s0 + r) * DIM + c] = (v[i] - m) * rs * olng[c] + olnb[c];
        }
    }
}

extern "C" void kernel_launch(void* const* d_in, const int* in_sizes, int n_in,
                              void* d_out, int out_size) {
    const float* ge      = (const float*)d_in[0];
    const float* pe      = (const float*)d_in[1];
    const float* sfeat   = (const float*)d_in[2];
    const float* ppi     = (const float*)d_in[3];
    const float* symW    = (const float*)d_in[4];
    const float* symb    = (const float*)d_in[5];
    const float* symg    = (const float*)d_in[6];
    const float* symbeta = (const float*)d_in[7];
    const float* tte     = (const float*)d_in[8];
    const float* Wqkv    = (const float*)d_in[9];
    const float* bqkv    = (const float*)d_in[10];
    const float* Wo      = (const float*)d_in[11];
    const float* bo      = (const float*)d_in[12];
    const float* ln1g    = (const float*)d_in[13];
    const float* ln1b    = (const float*)d_in[14];
    const float* ln2g    = (const float*)d_in[15];
    const float* ln2b    = (const float*)d_in[16];
    const float* W1      = (const float*)d_in[17];
    const float* b1      = (const float*)d_in[18];
    const float* W2      = (const float*)d_in[19];
    const float* b2      = (const float*)d_in[20];
    const float* flng    = (const float*)d_in[21];
    const float* flnb    = (const float*)d_in[22];
    const float* olng    = (const float*)d_in[23];
    const float* olnb    = (const float*)d_in[24];

    int B = in_sizes[0] / DIM;

    cudaFuncSetAttribute(fused_kernel, cudaFuncAttributeMaxDynamicSharedMemorySize, SMEM_BYTES);

    pack_all<<<1152, 256>>>(Wqkv, Wo, W1, W2);

    fused_kernel<<<B / TS, NTHREADS, SMEM_BYTES>>>(
        ge, pe, sfeat, ppi, symW, symb, symg, symbeta, tte,
        bqkv, bo, ln1g, ln1b, ln2g, ln2b, b1, b2,
        flng, flnb, olng, olnb, (float*)d_out);
}